// round 14
// baseline (speedup 1.0000x reference)
#include <cuda_runtime.h>
#include <cstdint>
#include <math.h>

#define BB 8
#define CC 256
#define NN 4096        // 64*64
#define WH 64
#define MMK 23
#define PADK 11
#define OCH 144        // 64 q + 16 k + 64 v

typedef unsigned int u32;

// ---- scratch (static device globals; no allocation anywhere) ----
__device__ float g_Wf[OCH * CC];          // BN-folded weights
__device__ float g_bf[OCH];               // folded bias
__device__ float g_q [BB * 64 * NN];      // q after BN
__device__ float g_kf[BB * 16 * NN];      // k, softmaxed in place
__device__ float g_v [BB * 64 * NN];      // v after BN
__device__ float g_lc[BB * 16 * 64];      // content lambda

__device__ __forceinline__ u32 f2tf32(float f)
{
    u32 u;
    asm("cvt.rna.tf32.f32 %0, %1;" : "=r"(u) : "f"(f));
    return u;
}

#define MMA_TF32(d, a, b) \
    asm("mma.sync.aligned.m16n8k8.row.col.f32.tf32.tf32.f32 " \
        "{%0,%1,%2,%3}, {%4,%5,%6,%7}, {%8,%9}, {%0,%1,%2,%3};" \
        : "+f"((d)[0]), "+f"((d)[1]), "+f"((d)[2]), "+f"((d)[3]) \
        : "r"((a)[0]), "r"((a)[1]), "r"((a)[2]), "r"((a)[3]), \
          "r"((b)[0]), "r"((b)[1]))

// ============ K0: fold BN into weights ============
__global__ void fold_kernel(const float* __restrict__ Wq,
                            const float* __restrict__ qg, const float* __restrict__ qb,
                            const float* __restrict__ qm, const float* __restrict__ qv,
                            const float* __restrict__ Wk, const float* __restrict__ Wv,
                            const float* __restrict__ vg, const float* __restrict__ vb,
                            const float* __restrict__ vm, const float* __restrict__ vvar)
{
    int o = blockIdx.x;
    int c = threadIdx.x;
    float w, bias = 0.f;
    if (o < 64) {
        float s = qg[o] * rsqrtf(qv[o] + 1e-5f);
        w = Wq[o * CC + c] * s;
        bias = qb[o] - qm[o] * s;
    } else if (o < 80) {
        int oo = o - 64;
        w = Wk[oo * CC + c];
    } else {
        int oo = o - 80;
        float s = vg[oo] * rsqrtf(vvar[oo] + 1e-5f);
        w = Wv[oo * CC + c] * s;
        bias = vb[oo] - vm[oo] * s;
    }
    g_Wf[o * CC + c] = w;
    if (c == 0) g_bf[o] = bias;
}

// ============ K1: zero lambda_c (graph replays -> must re-zero) ============
__global__ void zero_lc_kernel()
{
    int i = blockIdx.x * 256 + threadIdx.x;
    if (i < BB * 16 * 64) g_lc[i] = 0.f;
}

// ============ K2: projection GEMM via tf32 tensor cores (3xTF32) ============
// C[144,4096] = Wf[144,256] x X[256,4096] per batch. CTA tile 144 x 128,
// K-chunks of 32. Fragments pre-swizzled in smem: A frag = 1 LDS.128,
// B frag = 1 LDS.64. 3xTF32: C = Wb*Xb + Wb*Xs + Ws*Xb (fp32-grade accuracy).
// smem (u32): Wb 4608 | Ws 4608 | Xb 4096 | Xs 4096 = 17408 words = 69632 B
#define PROJ_SMEM_BYTES 69632

__global__ void __launch_bounds__(256, 2) proj_kernel(const float* __restrict__ x)
{
    extern __shared__ u32 smu[];
    u32* wbf = smu;            // [9 mt][4 k8][32 lane][4 slot]
    u32* wsf = smu + 4608;
    u32* xbf = smu + 9216;     // [16 nt][4 k8][32 lane][2 slot]
    u32* xsf = smu + 13312;

    const int b = blockIdx.y;
    const int n0 = blockIdx.x * 128;
    const int t = threadIdx.x;
    const int w = t >> 5, l = t & 31;

    float acc[9][2][4];
#pragma unroll
    for (int mt = 0; mt < 9; mt++)
#pragma unroll
        for (int j = 0; j < 2; j++)
#pragma unroll
            for (int e = 0; e < 4; e++) acc[mt][j][e] = 0.f;

#pragma unroll 1
    for (int kc = 0; kc < CC; kc += 32) {
        __syncthreads();   // previous chunk's mma reads done

        // ---- load W chunk [144][32], convert + pre-swizzle ----
        for (int i = t; i < 144 * 32; i += 256) {
            int o = i >> 5, k = i & 31;
            float wv = g_Wf[o * CC + kc + k];
            u32 big = f2tf32(wv);
            u32 sml = f2tf32(wv - __uint_as_float(big));
            int lane = (o & 7) * 4 + (k & 3);
            int slot = ((o >> 3) & 1) + (((k >> 2) & 1) << 1);
            int word = (((o >> 4) * 4 + (k >> 3)) * 32 + lane) * 4 + slot;
            wbf[word] = big;
            wsf[word] = sml;
        }
        // ---- load X chunk [32][128] (float4), convert + pre-swizzle ----
        for (int i = t; i < 32 * 32; i += 256) {
            int k = i >> 5, n4 = i & 31;
            float4 xv = *(const float4*)&x[((size_t)b * CC + kc + k) * NN + n0 + n4 * 4];
            float vals[4] = {xv.x, xv.y, xv.z, xv.w};
#pragma unroll
            for (int e = 0; e < 4; e++) {
                int n = n4 * 4 + e;
                u32 big = f2tf32(vals[e]);
                u32 sml = f2tf32(vals[e] - __uint_as_float(big));
                int lane = (n & 7) * 4 + (k & 3);
                int slot = (k >> 2) & 1;
                int word = (((n >> 3) * 4 + (k >> 3)) * 32 + lane) * 2 + slot;
                xbf[word] = big;
                xsf[word] = sml;
            }
        }
        __syncthreads();

        // ---- mma: warp w covers nt = 2w, 2w+1; all 9 m-tiles ----
#pragma unroll
        for (int k8 = 0; k8 < 4; k8++) {
            u32 Bb[2][2], Bs[2][2];
#pragma unroll
            for (int j = 0; j < 2; j++) {
                int base = (((2 * w + j) * 4 + k8) * 32 + l) * 2;
                Bb[j][0] = xbf[base]; Bb[j][1] = xbf[base + 1];
                Bs[j][0] = xsf[base]; Bs[j][1] = xsf[base + 1];
            }
#pragma unroll
            for (int mt = 0; mt < 9; mt++) {
                int base = ((mt * 4 + k8) * 32 + l) * 4;
                u32 Ab[4], As[4];
                *(uint4*)Ab = *(const uint4*)&wbf[base];
                *(uint4*)As = *(const uint4*)&wsf[base];
#pragma unroll
                for (int j = 0; j < 2; j++) {
                    MMA_TF32(acc[mt][j], Ab, Bb[j]);
                    MMA_TF32(acc[mt][j], Ab, Bs[j]);
                    MMA_TF32(acc[mt][j], As, Bb[j]);
                }
            }
        }
    }

    // ---- epilogue: bias + route to g_q / g_kf / g_v ----
    const int gid = l >> 2, tig = l & 3;
#pragma unroll
    for (int mt = 0; mt < 9; mt++) {
#pragma unroll
        for (int j = 0; j < 2; j++) {
            int nb = n0 + (2 * w + j) * 8 + tig * 2;
#pragma unroll
            for (int half = 0; half < 2; half++) {
                int o = mt * 16 + gid + half * 8;
                float bias = g_bf[o];
                float* dst;
                if (o < 64)       dst = &g_q [((size_t)b * 64 + o)        * NN];
                else if (o < 80)  dst = &g_kf[((size_t)b * 16 + (o - 64)) * NN];
                else              dst = &g_v [((size_t)b * 64 + (o - 80)) * NN];
                float2 val = make_float2(acc[mt][j][half * 2 + 0] + bias,
                                         acc[mt][j][half * 2 + 1] + bias);
                *(float2*)&dst[nb] = val;
            }
        }
    }
}

// ============ K3: softmax over n for each (b,k) row ============
__global__ void softmax_kernel()
{
    int row = blockIdx.x;                 // b*16 + k
    float* p = &g_kf[(size_t)row * NN];
    int t = threadIdx.x;
    __shared__ float red[256];

    float vals[16];
    float m = -1e30f;
#pragma unroll
    for (int i = 0; i < 16; i++) {
        vals[i] = p[t + 256 * i];
        m = fmaxf(m, vals[i]);
    }
    red[t] = m; __syncthreads();
    for (int s = 128; s > 0; s >>= 1) {
        if (t < s) red[t] = fmaxf(red[t], red[t + s]);
        __syncthreads();
    }
    m = red[0]; __syncthreads();

    float sum = 0.f;
#pragma unroll
    for (int i = 0; i < 16; i++) {
        vals[i] = __expf(vals[i] - m);
        sum += vals[i];
    }
    red[t] = sum; __syncthreads();
    for (int s = 128; s > 0; s >>= 1) {
        if (t < s) red[t] += red[t + s];
        __syncthreads();
    }
    float inv = 1.f / red[0];
#pragma unroll
    for (int i = 0; i < 16; i++) p[t + 256 * i] = vals[i] * inv;
}

// ============ K4: lambda_c[b,k,v] = sum_n kf[b,k,n]*v[b,v,n] ============
// vs padded to 129 floats/row: conflict-free column reads.
__global__ void __launch_bounds__(256) lambdac_kernel()
{
    __shared__ float kfs[16][128];
    __shared__ float vs[64][129];
    int b = blockIdx.y;
    int n0 = blockIdx.x * 128;
    int t = threadIdx.x;

    for (int i = t; i < 16 * 128; i += 256) {
        int k = i >> 7, n = i & 127;
        kfs[k][n] = g_kf[((size_t)b * 16 + k) * NN + n0 + n];
    }
    for (int i = t; i < 64 * 128; i += 256) {
        int v = i >> 7, n = i & 127;
        vs[v][n] = g_v[((size_t)b * 64 + v) * NN + n0 + n];
    }
    __syncthreads();

#pragma unroll
    for (int pq = 0; pq < 4; pq++) {
        int pid = t + 256 * pq;           // 0..1023
        int k = pid >> 6, v = pid & 63;
        float a = 0.f;
#pragma unroll 8
        for (int nn = 0; nn < 128; nn++) a += kfs[k][nn] * vs[v][nn];
        atomicAdd(&g_lc[(size_t)b * 1024 + pid], a);
    }
}

// ============ K5: fused positional lambda + output (v4 scalar, proven) ========
#define FUSED_SMEM_BYTES 100416

__global__ void __launch_bounds__(256, 2) fused_kernel(const float* __restrict__ emb,
                                                       float* __restrict__ out)
{
    extern __shared__ float sm[];
    float* q_s   = sm;            // [64 ch][64 c]
    float* lc_s  = sm + 4096;     // [16][64]
    float* emb_t = sm + 5120;     // [529 p][16 k]  (transposed)
    float* s_s   = sm + 13584;    // [4h][23dj][64c]
    float* vr_s  = sm + 19472;    // [64v][88]

    const int r = blockIdx.x, b = blockIdx.y;
    const int t = threadIdx.x;
    const int w = t >> 5, l = t & 31;

    const int strip  = (l & 7) | ((w & 1) << 3);
    const int vgroup = (l >> 3) | ((w >> 1) << 2);
    const int c0 = strip * 4, v0 = vgroup * 4;

    const int hh  = w & 3;
    const int djb = ((w >> 2) * 12) + ((l >> 4) * 6);   // 0,6,12,18
    const int cq  = l & 15;

    const int col = t & 63, vv0 = t >> 6;

    for (int i = t; i < 4096; i += 256) {
        int ch = i >> 6, c = i & 63;
        q_s[i] = g_q[((size_t)b * 64 + ch) * NN + r * WH + c];
    }
    for (int i = t; i < 1024; i += 256) lc_s[i] = g_lc[b * 1024 + i];
    for (int i = t; i < 8464; i += 256) {
        int p = i >> 4, k = i & 15;               // transpose on load
        emb_t[i] = emb[k * 529 + p];
    }
    for (int i = t; i < 5632; i += 256) vr_s[i] = 0.f;   // halo stays zero
    __syncthreads();

    float acc[4][4][4];
#pragma unroll
    for (int h = 0; h < 4; h++)
#pragma unroll
        for (int v = 0; v < 4; v++)
#pragma unroll
            for (int c = 0; c < 4; c++) acc[h][v][c] = 0.f;

    const float4* q4 = (const float4*)q_s;          // [64 ch][16] float4
#pragma unroll
    for (int k = 0; k < 16; k++) {
        float lv[4];
#pragma unroll
        for (int v = 0; v < 4; v++) lv[v] = lc_s[k * 64 + v0 + v];
#pragma unroll
        for (int h = 0; h < 4; h++) {
            float4 qv = q4[(h * 16 + k) * 16 + strip];
#pragma unroll
            for (int v = 0; v < 4; v++) {
                acc[h][v][0] += qv.x * lv[v]; acc[h][v][1] += qv.y * lv[v];
                acc[h][v][2] += qv.z * lv[v]; acc[h][v][3] += qv.w * lv[v];
            }
        }
    }

    const int di_lo = (r < PADK) ? (PADK - r) : 0;
    const int di_hi = (r > 52) ? (74 - r) : 22;
    const float* vbase = &g_v[(size_t)b * 64 * NN];
    float4* s4 = (float4*)s_s;                      // [4*23][16] float4

#pragma unroll 1
    for (int di = di_lo; di <= di_hi; di++) {
        const int rr = r + di - PADK;
        __syncthreads();   // A: previous apply done reading s_s / vr_s

        float vreg[16];
#pragma unroll
        for (int i = 0; i < 16; i++)
            vreg[i] = vbase[(size_t)(4 * i + vv0) * NN + rr * WH + col];

        {
            float4 sv[6];
#pragma unroll
            for (int j = 0; j < 6; j++) sv[j] = make_float4(0.f, 0.f, 0.f, 0.f);

            const float* ebase = &emb_t[(di * MMK) * 16];
#pragma unroll
            for (int kc = 0; kc < 4; kc++) {
                float4 qr[4];
#pragma unroll
                for (int kk = 0; kk < 4; kk++)
                    qr[kk] = q4[(hh * 16 + kc * 4 + kk) * 16 + cq];
#pragma unroll
                for (int j = 0; j < 6; j++) {
                    const int dj = djb + j;
                    if (dj < MMK) {
                        float4 ew = *(const float4*)&ebase[dj * 16 + kc * 4];
                        sv[j].x += ew.x * qr[0].x + ew.y * qr[1].x
                                 + ew.z * qr[2].x + ew.w * qr[3].x;
                        sv[j].y += ew.x * qr[0].y + ew.y * qr[1].y
                                 + ew.z * qr[2].y + ew.w * qr[3].y;
                        sv[j].z += ew.x * qr[0].z + ew.y * qr[1].z
                                 + ew.z * qr[2].z + ew.w * qr[3].z;
                        sv[j].w += ew.x * qr[0].w + ew.y * qr[1].w
                                 + ew.z * qr[2].w + ew.w * qr[3].w;
                    }
                }
            }
#pragma unroll
            for (int j = 0; j < 6; j++) {
                const int dj = djb + j;
                if (dj < MMK) s4[(hh * 23 + dj) * 16 + cq] = sv[j];
            }
        }

#pragma unroll
        for (int i = 0; i < 16; i++)
            vr_s[(4 * i + vv0) * 88 + PADK + col] = vreg[i];
        __syncthreads();   // B: s_s and vr_s ready

        float vw[4][8];
#pragma unroll
        for (int v = 0; v < 4; v++) {
            float4 a0 = *(const float4*)&vr_s[(v0 + v) * 88 + c0];
            float4 a1 = *(const float4*)&vr_s[(v0 + v) * 88 + c0 + 4];
            vw[v][0] = a0.x; vw[v][1] = a0.y; vw[v][2] = a0.z; vw[v][3] = a0.w;
            vw[v][4] = a1.x; vw[v][5] = a1.y; vw[v][6] = a1.z; vw[v][7] = a1.w;
        }

#pragma unroll
        for (int djq = 0; djq < 6; djq++) {
#pragma unroll
            for (int djl = 0; djl < 4; djl++) {
                const int dj = djq * 4 + djl;
                if (dj < MMK) {
                    float4 sh[4];
#pragma unroll
                    for (int h = 0; h < 4; h++)
                        sh[h] = s4[(h * 23 + dj) * 16 + strip];
#pragma unroll
                    for (int h = 0; h < 4; h++)
#pragma unroll
                        for (int v = 0; v < 4; v++) {
                            acc[h][v][0] += sh[h].x * vw[v][djl + 0];
                            acc[h][v][1] += sh[h].y * vw[v][djl + 1];
                            acc[h][v][2] += sh[h].z * vw[v][djl + 2];
                            acc[h][v][3] += sh[h].w * vw[v][djl + 3];
                        }
                }
            }
            if (djq < 5) {
#pragma unroll
                for (int v = 0; v < 4; v++) {
                    vw[v][0] = vw[v][4]; vw[v][1] = vw[v][5];
                    vw[v][2] = vw[v][6]; vw[v][3] = vw[v][7];
                    float4 nx = *(const float4*)&vr_s[(v0 + v) * 88 + c0 + (djq + 2) * 4];
                    vw[v][4] = nx.x; vw[v][5] = nx.y; vw[v][6] = nx.z; vw[v][7] = nx.w;
                }
            }
        }
    }

#pragma unroll
    for (int h = 0; h < 4; h++)
#pragma unroll
        for (int v = 0; v < 4; v++) {
            float4 o4 = make_float4(acc[h][v][0], acc[h][v][1],
                                    acc[h][v][2], acc[h][v][3]);
            *(float4*)&out[((size_t)b * 256 + h * 64 + v0 + v) * NN + r * WH + c0] = o4;
        }
}

// ============ launcher ============
extern "C" void kernel_launch(void* const* d_in, const int* in_sizes, int n_in,
                              void* d_out, int out_size)
{
    const float* x   = (const float*)d_in[0];
    const float* Wq  = (const float*)d_in[1];
    const float* qg  = (const float*)d_in[2];
    const float* qb  = (const float*)d_in[3];
    const float* qm  = (const float*)d_in[4];
    const float* qv  = (const float*)d_in[5];
    const float* Wk  = (const float*)d_in[6];
    const float* Wv  = (const float*)d_in[7];
    const float* vg  = (const float*)d_in[8];
    const float* vb  = (const float*)d_in[9];
    const float* vm  = (const float*)d_in[10];
    const float* vvr = (const float*)d_in[11];
    const float* emb = (const float*)d_in[12];
    float* out = (float*)d_out;

    cudaFuncSetAttribute(fused_kernel,
                         cudaFuncAttributeMaxDynamicSharedMemorySize,
                         FUSED_SMEM_BYTES);
    cudaFuncSetAttribute(proj_kernel,
                         cudaFuncAttributeMaxDynamicSharedMemorySize,
                         PROJ_SMEM_BYTES);

    fold_kernel<<<OCH, 256>>>(Wq, qg, qb, qm, qv, Wk, Wv, vg, vb, vm, vvr);
    zero_lc_kernel<<<(BB * 16 * 64 + 255) / 256, 256>>>();
    proj_kernel<<<dim3(32, BB), 256, PROJ_SMEM_BYTES>>>(x);
    softmax_kernel<<<BB * 16, 256>>>();
    lambdac_kernel<<<dim3(32, BB), 256>>>();
    fused_kernel<<<dim3(WH, BB), 256, FUSED_SMEM_BYTES>>>(emb, out);
}

// round 15
// speedup vs baseline: 1.1840x; 1.1840x over previous
#include <cuda_runtime.h>
#include <cstdint>
#include <math.h>

#define BB 8
#define CC 256
#define NN 4096        // 64*64
#define WH 64
#define MMK 23
#define PADK 11
#define OCH 144        // 64 q + 16 k + 64 v

typedef unsigned int u32;

#define MMA_TF32(d, a, b) \
    asm("mma.sync.aligned.m16n8k8.row.col.f32.tf32.tf32.f32 " \
        "{%0,%1,%2,%3}, {%4,%5,%6,%7}, {%8,%9}, {%0,%1,%2,%3};" \
        : "+f"((d)[0]), "+f"((d)[1]), "+f"((d)[2]), "+f"((d)[3]) \
        : "r"((a)[0]), "r"((a)[1]), "r"((a)[2]), "r"((a)[3]), \
          "r"((b)[0]), "r"((b)[1]))

// ---- scratch (static device globals; no allocation anywhere) ----
__device__ float g_Wf[OCH * CC];          // BN-folded weights
__device__ float g_bf[OCH];               // folded bias
__device__ __align__(16) u32 g_wbf[8 * 4608];  // W tf32 "big" frags, swizzled
__device__ __align__(16) u32 g_wsf[8 * 4608];  // W tf32 residual frags
__device__ float g_q [BB * 64 * NN];      // q after BN
__device__ float g_kf[BB * 16 * NN];      // k, softmaxed in place
__device__ float g_v [BB * 64 * NN];      // v after BN
__device__ float g_lc[BB * 16 * 64];      // content lambda

// ============ K0: fold BN into weights + precompute W tf32 fragments ============
__global__ void fold_kernel(const float* __restrict__ Wq,
                            const float* __restrict__ qg, const float* __restrict__ qb,
                            const float* __restrict__ qm, const float* __restrict__ qv,
                            const float* __restrict__ Wk, const float* __restrict__ Wv,
                            const float* __restrict__ vg, const float* __restrict__ vb,
                            const float* __restrict__ vm, const float* __restrict__ vvar)
{
    int o = blockIdx.x;
    int c = threadIdx.x;
    float w, bias = 0.f;
    if (o < 64) {
        float s = qg[o] * rsqrtf(qv[o] + 1e-5f);
        w = Wq[o * CC + c] * s;
        bias = qb[o] - qm[o] * s;
    } else if (o < 80) {
        int oo = o - 64;
        w = Wk[oo * CC + c];
    } else {
        int oo = o - 80;
        float s = vg[oo] * rsqrtf(vvar[oo] + 1e-5f);
        w = Wv[oo * CC + c] * s;
        bias = vb[oo] - vm[oo] * s;
    }
    g_Wf[o * CC + c] = w;
    if (c == 0) g_bf[o] = bias;

    // tf32 split (truncation) + fragment swizzle, computed ONCE
    int chunk = c >> 5, k = c & 31;
    u32 big = __float_as_uint(w) & 0xFFFFE000u;
    float rs = w - __uint_as_float(big);
    u32 sml = __float_as_uint(rs) & 0xFFFFE000u;
    int word = chunk * 4608
             + (((o >> 4) * 4 + (k >> 3)) * 32 + (o & 7) * 4 + (k & 3)) * 4
             + ((o >> 3) & 1) + (((k >> 2) & 1) << 1);
    g_wbf[word] = big;
    g_wsf[word] = sml;
}

// ============ K1: zero lambda_c (graph replays -> must re-zero) ============
__global__ void zero_lc_kernel()
{
    int i = blockIdx.x * 256 + threadIdx.x;
    if (i < BB * 16 * 64) g_lc[i] = 0.f;
}

// ============ K2: projection GEMM via tf32 tensor cores (3xTF32, v2) ============
// C[144,4096] = Wf[144,256] x X[256,4096] per batch. CTA tile 144 x 128.
// W frags: precomputed in fold, staged via plain uint4 copy.
// X frags: layout [4 k8][2 slot][16 nt][33] -> conflict-free STS and LDS.
// smem (u32): wbf 4608 | wsf 4608 | xbf 4224 | xsf 4224 = 17664 w = 70656 B
#define PROJ_SMEM_BYTES 70656

__global__ void __launch_bounds__(256, 2) proj_kernel(const float* __restrict__ x)
{
    extern __shared__ u32 smu[];
    u32* wbf = smu;            // [9 mt][4 k8][32 lane][4 slot]
    u32* wsf = smu + 4608;
    u32* xbf = smu + 9216;     // [4 k8][2 slot][16 nt][33]
    u32* xsf = smu + 13440;

    const int b = blockIdx.y;
    const int n0 = blockIdx.x * 128;
    const int t = threadIdx.x;
    const int w = t >> 5, l = t & 31;

    // X element mapping: k0 = t>>5 (0..7), n4 = t&31; k = k0 + 8m
    const int k0 = t >> 5;
    const int n4 = t & 31;
    const int slotX = (k0 >> 2) & 1;
    const int k3 = k0 & 3;

    float acc[9][2][4];
#pragma unroll
    for (int mt = 0; mt < 9; mt++)
#pragma unroll
        for (int j = 0; j < 2; j++)
#pragma unroll
            for (int e = 0; e < 4; e++) acc[mt][j][e] = 0.f;

#pragma unroll 1
    for (int kc = 0; kc < CC; kc += 32) {
        __syncthreads();   // previous chunk's reads done
        const int chunk = kc >> 5;

        // ---- stage W fragments (plain copy, conflict-free) ----
        {
            const uint4* srcb = (const uint4*)(g_wbf + chunk * 4608);
            const uint4* srcs = (const uint4*)(g_wsf + chunk * 4608);
            for (int i = t; i < 1152; i += 256) {
                ((uint4*)wbf)[i] = srcb[i];
                ((uint4*)wsf)[i] = srcs[i];
            }
        }
        // ---- convert X chunk into fragments (conflict-free STS) ----
#pragma unroll
        for (int m = 0; m < 4; m++) {
            const int k = k0 + 8 * m;
            float4 xv = *(const float4*)&x[((size_t)b * CC + kc + k) * NN + n0 + n4 * 4];
            float vals[4] = {xv.x, xv.y, xv.z, xv.w};
#pragma unroll
            for (int e = 0; e < 4; e++) {
                const int n = n4 * 4 + e;
                u32 big = __float_as_uint(vals[e]) & 0xFFFFE000u;
                float rs = vals[e] - __uint_as_float(big);
                u32 sml = __float_as_uint(rs) & 0xFFFFE000u;
                int word = ((m * 2 + slotX) * 16 + (n >> 3)) * 33 + (n & 7) * 4 + k3;
                xbf[word] = big;
                xsf[word] = sml;
            }
        }
        __syncthreads();

        // ---- mma: warp w covers nt = 2w, 2w+1; all 9 m-tiles ----
#pragma unroll
        for (int k8 = 0; k8 < 4; k8++) {
            u32 Bb[2][2], Bs[2][2];
#pragma unroll
            for (int j = 0; j < 2; j++) {
                const int ntj = 2 * w + j;
                const int b0 = ((k8 * 2 + 0) * 16 + ntj) * 33 + l;
                const int b1 = ((k8 * 2 + 1) * 16 + ntj) * 33 + l;
                Bb[j][0] = xbf[b0]; Bb[j][1] = xbf[b1];
                Bs[j][0] = xsf[b0]; Bs[j][1] = xsf[b1];
            }
#pragma unroll
            for (int mt = 0; mt < 9; mt++) {
                const int base = ((mt * 4 + k8) * 32 + l) * 4;
                u32 Ab[4], As[4];
                *(uint4*)Ab = *(const uint4*)&wbf[base];
                *(uint4*)As = *(const uint4*)&wsf[base];
#pragma unroll
                for (int j = 0; j < 2; j++) {
                    MMA_TF32(acc[mt][j], Ab, Bb[j]);
                    MMA_TF32(acc[mt][j], Ab, Bs[j]);
                    MMA_TF32(acc[mt][j], As, Bb[j]);
                }
            }
        }
    }

    // ---- epilogue: bias + route to g_q / g_kf / g_v (validated in r14) ----
    const int gid = l >> 2, tig = l & 3;
#pragma unroll
    for (int mt = 0; mt < 9; mt++) {
#pragma unroll
        for (int j = 0; j < 2; j++) {
            int nb = n0 + (2 * w + j) * 8 + tig * 2;
#pragma unroll
            for (int half = 0; half < 2; half++) {
                int o = mt * 16 + gid + half * 8;
                float bias = g_bf[o];
                float* dst;
                if (o < 64)       dst = &g_q [((size_t)b * 64 + o)        * NN];
                else if (o < 80)  dst = &g_kf[((size_t)b * 16 + (o - 64)) * NN];
                else              dst = &g_v [((size_t)b * 64 + (o - 80)) * NN];
                float2 val = make_float2(acc[mt][j][half * 2 + 0] + bias,
                                         acc[mt][j][half * 2 + 1] + bias);
                *(float2*)&dst[nb] = val;
            }
        }
    }
}

// ============ K3: softmax over n for each (b,k) row ============
__global__ void softmax_kernel()
{
    int row = blockIdx.x;                 // b*16 + k
    float* p = &g_kf[(size_t)row * NN];
    int t = threadIdx.x;
    __shared__ float red[256];

    float vals[16];
    float m = -1e30f;
#pragma unroll
    for (int i = 0; i < 16; i++) {
        vals[i] = p[t + 256 * i];
        m = fmaxf(m, vals[i]);
    }
    red[t] = m; __syncthreads();
    for (int s = 128; s > 0; s >>= 1) {
        if (t < s) red[t] = fmaxf(red[t], red[t + s]);
        __syncthreads();
    }
    m = red[0]; __syncthreads();

    float sum = 0.f;
#pragma unroll
    for (int i = 0; i < 16; i++) {
        vals[i] = __expf(vals[i] - m);
        sum += vals[i];
    }
    red[t] = sum; __syncthreads();
    for (int s = 128; s > 0; s >>= 1) {
        if (t < s) red[t] += red[t + s];
        __syncthreads();
    }
    float inv = 1.f / red[0];
#pragma unroll
    for (int i = 0; i < 16; i++) p[t + 256 * i] = vals[i] * inv;
}

// ============ K4: lambda_c[b,k,v] = sum_n kf[b,k,n]*v[b,v,n] ============
// vs padded to 129 floats/row: conflict-free column reads.
__global__ void __launch_bounds__(256) lambdac_kernel()
{
    __shared__ float kfs[16][128];
    __shared__ float vs[64][129];
    int b = blockIdx.y;
    int n0 = blockIdx.x * 128;
    int t = threadIdx.x;

    for (int i = t; i < 16 * 128; i += 256) {
        int k = i >> 7, n = i & 127;
        kfs[k][n] = g_kf[((size_t)b * 16 + k) * NN + n0 + n];
    }
    for (int i = t; i < 64 * 128; i += 256) {
        int v = i >> 7, n = i & 127;
        vs[v][n] = g_v[((size_t)b * 64 + v) * NN + n0 + n];
    }
    __syncthreads();

#pragma unroll
    for (int pq = 0; pq < 4; pq++) {
        int pid = t + 256 * pq;           // 0..1023
        int k = pid >> 6, v = pid & 63;
        float a = 0.f;
#pragma unroll 8
        for (int nn = 0; nn < 128; nn++) a += kfs[k][nn] * vs[v][nn];
        atomicAdd(&g_lc[(size_t)b * 1024 + pid], a);
    }
}

// ============ K5: fused positional lambda + output (v4 scalar, frozen) ========
#define FUSED_SMEM_BYTES 100416

__global__ void __launch_bounds__(256, 2) fused_kernel(const float* __restrict__ emb,
                                                       float* __restrict__ out)
{
    extern __shared__ float sm[];
    float* q_s   = sm;            // [64 ch][64 c]
    float* lc_s  = sm + 4096;     // [16][64]
    float* emb_t = sm + 5120;     // [529 p][16 k]  (transposed)
    float* s_s   = sm + 13584;    // [4h][23dj][64c]
    float* vr_s  = sm + 19472;    // [64v][88]

    const int r = blockIdx.x, b = blockIdx.y;
    const int t = threadIdx.x;
    const int w = t >> 5, l = t & 31;

    const int strip  = (l & 7) | ((w & 1) << 3);
    const int vgroup = (l >> 3) | ((w >> 1) << 2);
    const int c0 = strip * 4, v0 = vgroup * 4;

    const int hh  = w & 3;
    const int djb = ((w >> 2) * 12) + ((l >> 4) * 6);   // 0,6,12,18
    const int cq  = l & 15;

    const int col = t & 63, vv0 = t >> 6;

    for (int i = t; i < 4096; i += 256) {
        int ch = i >> 6, c = i & 63;
        q_s[i] = g_q[((size_t)b * 64 + ch) * NN + r * WH + c];
    }
    for (int i = t; i < 1024; i += 256) lc_s[i] = g_lc[b * 1024 + i];
    for (int i = t; i < 8464; i += 256) {
        int p = i >> 4, k = i & 15;               // transpose on load
        emb_t[i] = emb[k * 529 + p];
    }
    for (int i = t; i < 5632; i += 256) vr_s[i] = 0.f;   // halo stays zero
    __syncthreads();

    float acc[4][4][4];
#pragma unroll
    for (int h = 0; h < 4; h++)
#pragma unroll
        for (int v = 0; v < 4; v++)
#pragma unroll
            for (int c = 0; c < 4; c++) acc[h][v][c] = 0.f;

    const float4* q4 = (const float4*)q_s;          // [64 ch][16] float4
#pragma unroll
    for (int k = 0; k < 16; k++) {
        float lv[4];
#pragma unroll
        for (int v = 0; v < 4; v++) lv[v] = lc_s[k * 64 + v0 + v];
#pragma unroll
        for (int h = 0; h < 4; h++) {
            float4 qv = q4[(h * 16 + k) * 16 + strip];
#pragma unroll
            for (int v = 0; v < 4; v++) {
                acc[h][v][0] += qv.x * lv[v]; acc[h][v][1] += qv.y * lv[v];
                acc[h][v][2] += qv.z * lv[v]; acc[h][v][3] += qv.w * lv[v];
            }
        }
    }

    const int di_lo = (r < PADK) ? (PADK - r) : 0;
    const int di_hi = (r > 52) ? (74 - r) : 22;
    const float* vbase = &g_v[(size_t)b * 64 * NN];
    float4* s4 = (float4*)s_s;                      // [4*23][16] float4

#pragma unroll 1
    for (int di = di_lo; di <= di_hi; di++) {
        const int rr = r + di - PADK;
        __syncthreads();   // A

        float vreg[16];
#pragma unroll
        for (int i = 0; i < 16; i++)
            vreg[i] = vbase[(size_t)(4 * i + vv0) * NN + rr * WH + col];

        {
            float4 sv[6];
#pragma unroll
            for (int j = 0; j < 6; j++) sv[j] = make_float4(0.f, 0.f, 0.f, 0.f);

            const float* ebase = &emb_t[(di * MMK) * 16];
#pragma unroll
            for (int kc = 0; kc < 4; kc++) {
                float4 qr[4];
#pragma unroll
                for (int kk = 0; kk < 4; kk++)
                    qr[kk] = q4[(hh * 16 + kc * 4 + kk) * 16 + cq];
#pragma unroll
                for (int j = 0; j < 6; j++) {
                    const int dj = djb + j;
                    if (dj < MMK) {
                        float4 ew = *(const float4*)&ebase[dj * 16 + kc * 4];
                        sv[j].x += ew.x * qr[0].x + ew.y * qr[1].x
                                 + ew.z * qr[2].x + ew.w * qr[3].x;
                        sv[j].y += ew.x * qr[0].y + ew.y * qr[1].y
                                 + ew.z * qr[2].y + ew.w * qr[3].y;
                        sv[j].z += ew.x * qr[0].z + ew.y * qr[1].z
                                 + ew.z * qr[2].z + ew.w * qr[3].z;
                        sv[j].w += ew.x * qr[0].w + ew.y * qr[1].w
                                 + ew.z * qr[2].w + ew.w * qr[3].w;
                    }
                }
            }
#pragma unroll
            for (int j = 0; j < 6; j++) {
                const int dj = djb + j;
                if (dj < MMK) s4[(hh * 23 + dj) * 16 + cq] = sv[j];
            }
        }

#pragma unroll
        for (int i = 0; i < 16; i++)
            vr_s[(4 * i + vv0) * 88 + PADK + col] = vreg[i];
        __syncthreads();   // B

        float vw[4][8];
#pragma unroll
        for (int v = 0; v < 4; v++) {
            float4 a0 = *(const float4*)&vr_s[(v0 + v) * 88 + c0];
            float4 a1 = *(const float4*)&vr_s[(v0 + v) * 88 + c0 + 4];
            vw[v][0] = a0.x; vw[v][1] = a0.y; vw[v][2] = a0.z; vw[v][3] = a0.w;
            vw[v][4] = a1.x; vw[v][5] = a1.y; vw[v][6] = a1.z; vw[v][7] = a1.w;
        }

#pragma unroll
        for (int djq = 0; djq < 6; djq++) {
#pragma unroll
            for (int djl = 0; djl < 4; djl++) {
                const int dj = djq * 4 + djl;
                if (dj < MMK) {
                    float4 sh[4];
#pragma unroll
                    for (int h = 0; h < 4; h++)
                        sh[h] = s4[(h * 23 + dj) * 16 + strip];
#pragma unroll
                    for (int h = 0; h < 4; h++)
#pragma unroll
                        for (int v = 0; v < 4; v++) {
                            acc[h][v][0] += sh[h].x * vw[v][djl + 0];
                            acc[h][v][1] += sh[h].y * vw[v][djl + 1];
                            acc[h][v][2] += sh[h].z * vw[v][djl + 2];
                            acc[h][v][3] += sh[h].w * vw[v][djl + 3];
                        }
                }
            }
            if (djq < 5) {
#pragma unroll
                for (int v = 0; v < 4; v++) {
                    vw[v][0] = vw[v][4]; vw[v][1] = vw[v][5];
                    vw[v][2] = vw[v][6]; vw[v][3] = vw[v][7];
                    float4 nx = *(const float4*)&vr_s[(v0 + v) * 88 + c0 + (djq + 2) * 4];
                    vw[v][4] = nx.x; vw[v][5] = nx.y; vw[v][6] = nx.z; vw[v][7] = nx.w;
                }
            }
        }
    }

#pragma unroll
    for (int h = 0; h < 4; h++)
#pragma unroll
        for (int v = 0; v < 4; v++) {
            float4 o4 = make_float4(acc[h][v][0], acc[h][v][1],
                                    acc[h][v][2], acc[h][v][3]);
            *(float4*)&out[((size_t)b * 256 + h * 64 + v0 + v) * NN + r * WH + c0] = o4;
        }
}

// ============ launcher ============
extern "C" void kernel_launch(void* const* d_in, const int* in_sizes, int n_in,
                              void* d_out, int out_size)
{
    const float* x   = (const float*)d_in[0];
    const float* Wq  = (const float*)d_in[1];
    const float* qg  = (const float*)d_in[2];
    const float* qb  = (const float*)d_in[3];
    const float* qm  = (const float*)d_in[4];
    const float* qv  = (const float*)d_in[5];
    const float* Wk  = (const float*)d_in[6];
    const float* Wv  = (const float*)d_in[7];
    const float* vg  = (const float*)d_in[8];
    const float* vb  = (const float*)d_in[9];
    const float* vm  = (const float*)d_in[10];
    const float* vvr = (const float*)d_in[11];
    const float* emb = (const float*)d_in[12];
    float* out = (float*)d_out;

    cudaFuncSetAttribute(fused_kernel,
                         cudaFuncAttributeMaxDynamicSharedMemorySize,
                         FUSED_SMEM_BYTES);
    cudaFuncSetAttribute(proj_kernel,
                         cudaFuncAttributeMaxDynamicSharedMemorySize,
                         PROJ_SMEM_BYTES);

    fold_kernel<<<OCH, 256>>>(Wq, qg, qb, qm, qv, Wk, Wv, vg, vb, vm, vvr);
    zero_lc_kernel<<<(BB * 16 * 64 + 255) / 256, 256>>>();
    proj_kernel<<<dim3(32, BB), 256, PROJ_SMEM_BYTES>>>(x);
    softmax_kernel<<<BB * 16, 256>>>();
    lambdac_kernel<<<dim3(32, BB), 256>>>();
    fused_kernel<<<dim3(WH, BB), 256, FUSED_SMEM_BYTES>>>(emb, out);
}

// round 16
// speedup vs baseline: 1.2273x; 1.0366x over previous
#include <cuda_runtime.h>
#include <cstdint>
#include <math.h>

#define BB 8
#define CC 256
#define NN 4096        // 64*64
#define WH 64
#define MMK 23
#define PADK 11
#define OCH 144        // 64 q + 16 k + 64 v

typedef unsigned int u32;

#define MMA_TF32(d, a, b) \
    asm("mma.sync.aligned.m16n8k8.row.col.f32.tf32.tf32.f32 " \
        "{%0,%1,%2,%3}, {%4,%5,%6,%7}, {%8,%9}, {%0,%1,%2,%3};" \
        : "+f"((d)[0]), "+f"((d)[1]), "+f"((d)[2]), "+f"((d)[3]) \
        : "r"((a)[0]), "r"((a)[1]), "r"((a)[2]), "r"((a)[3]), \
          "r"((b)[0]), "r"((b)[1]))

// ---- scratch (static device globals; no allocation anywhere) ----
__device__ float g_Wf[OCH * CC];          // BN-folded weights
__device__ float g_bf[OCH];               // folded bias
__device__ __align__(16) u32 g_wbf[8 * 4608];  // W tf32 "big" frags (proj)
__device__ __align__(16) u32 g_wsf[8 * 4608];  // W tf32 residual frags
__device__ __align__(16) u32 g_efb[23 * 2 * 2 * 128];  // emb A-frags big
__device__ __align__(16) u32 g_efs[23 * 2 * 2 * 128];  // emb A-frags small
__device__ float g_q [BB * 64 * NN];      // q after BN
__device__ float g_kf[BB * 16 * NN];      // k, softmaxed in place
__device__ float g_v [BB * 64 * NN];      // v after BN
__device__ float g_lc[BB * 16 * 64];      // content lambda

// ============ K0: fold BN + precompute W frags + emb A-frags ============
__global__ void fold_kernel(const float* __restrict__ Wq,
                            const float* __restrict__ qg, const float* __restrict__ qb,
                            const float* __restrict__ qm, const float* __restrict__ qv,
                            const float* __restrict__ Wk, const float* __restrict__ Wv,
                            const float* __restrict__ vg, const float* __restrict__ vb,
                            const float* __restrict__ vm, const float* __restrict__ vvar,
                            const float* __restrict__ emb)
{
    int o = blockIdx.x;
    int c = threadIdx.x;
    float w, bias = 0.f;
    if (o < 64) {
        float s = qg[o] * rsqrtf(qv[o] + 1e-5f);
        w = Wq[o * CC + c] * s;
        bias = qb[o] - qm[o] * s;
    } else if (o < 80) {
        int oo = o - 64;
        w = Wk[oo * CC + c];
    } else {
        int oo = o - 80;
        float s = vg[oo] * rsqrtf(vvar[oo] + 1e-5f);
        w = Wv[oo * CC + c] * s;
        bias = vb[oo] - vm[oo] * s;
    }
    g_Wf[o * CC + c] = w;
    if (c == 0) g_bf[o] = bias;

    // W tf32 fragments (validated in r15)
    {
        int chunk = c >> 5, k = c & 31;
        u32 big = __float_as_uint(w) & 0xFFFFE000u;
        float rs = w - __uint_as_float(big);
        u32 sml = __float_as_uint(rs) & 0xFFFFE000u;
        int word = chunk * 4608
                 + (((o >> 4) * 4 + (k >> 3)) * 32 + (o & 7) * 4 + (k & 3)) * 4
                 + ((o >> 3) & 1) + (((k >> 2) & 1) << 1);
        g_wbf[word] = big;
        g_wsf[word] = sml;
    }

    // emb A-fragments: per di, A[dj(pad 32)][k 16], same swizzle as W
    if (o < MMK) {
#pragma unroll
        for (int e = 0; e < 2; e++) {
            int idx = c + 256 * e;        // 0..511
            int dj = idx >> 4;            // 0..31
            int k  = idx & 15;
            float val = (dj < MMK) ? emb[k * 529 + o * MMK + dj] : 0.f;
            u32 big = __float_as_uint(val) & 0xFFFFE000u;
            float rs = val - __uint_as_float(big);
            u32 sml = __float_as_uint(rs) & 0xFFFFE000u;
            int word = ((o * 2 + (dj >> 4)) * 2 + (k >> 3)) * 128
                     + ((dj & 7) * 4 + (k & 3)) * 4
                     + ((dj >> 3) & 1) + (((k >> 2) & 1) << 1);
            g_efb[word] = big;
            g_efs[word] = sml;
        }
    }
}

// ============ K1: zero lambda_c (graph replays -> must re-zero) ============
__global__ void zero_lc_kernel()
{
    int i = blockIdx.x * 256 + threadIdx.x;
    if (i < BB * 16 * 64) g_lc[i] = 0.f;
}

// ============ K2: projection GEMM via tf32 tensor cores (r15, proven) ============
#define PROJ_SMEM_BYTES 70656

__global__ void __launch_bounds__(256, 2) proj_kernel(const float* __restrict__ x)
{
    extern __shared__ u32 smu[];
    u32* wbf = smu;            // [9 mt][4 k8][32 lane][4 slot]
    u32* wsf = smu + 4608;
    u32* xbf = smu + 9216;     // [4 k8][2 slot][16 nt][33]
    u32* xsf = smu + 13440;

    const int b = blockIdx.y;
    const int n0 = blockIdx.x * 128;
    const int t = threadIdx.x;
    const int w = t >> 5, l = t & 31;

    const int k0 = t >> 5;
    const int n4 = t & 31;
    const int slotX = (k0 >> 2) & 1;
    const int k3 = k0 & 3;

    float acc[9][2][4];
#pragma unroll
    for (int mt = 0; mt < 9; mt++)
#pragma unroll
        for (int j = 0; j < 2; j++)
#pragma unroll
            for (int e = 0; e < 4; e++) acc[mt][j][e] = 0.f;

#pragma unroll 1
    for (int kc = 0; kc < CC; kc += 32) {
        __syncthreads();
        const int chunk = kc >> 5;

        {
            const uint4* srcb = (const uint4*)(g_wbf + chunk * 4608);
            const uint4* srcs = (const uint4*)(g_wsf + chunk * 4608);
            for (int i = t; i < 1152; i += 256) {
                ((uint4*)wbf)[i] = srcb[i];
                ((uint4*)wsf)[i] = srcs[i];
            }
        }
#pragma unroll
        for (int m = 0; m < 4; m++) {
            const int k = k0 + 8 * m;
            float4 xv = *(const float4*)&x[((size_t)b * CC + kc + k) * NN + n0 + n4 * 4];
            float vals[4] = {xv.x, xv.y, xv.z, xv.w};
#pragma unroll
            for (int e = 0; e < 4; e++) {
                const int n = n4 * 4 + e;
                u32 big = __float_as_uint(vals[e]) & 0xFFFFE000u;
                float rs = vals[e] - __uint_as_float(big);
                u32 sml = __float_as_uint(rs) & 0xFFFFE000u;
                int word = ((m * 2 + slotX) * 16 + (n >> 3)) * 33 + (n & 7) * 4 + k3;
                xbf[word] = big;
                xsf[word] = sml;
            }
        }
        __syncthreads();

#pragma unroll
        for (int k8 = 0; k8 < 4; k8++) {
            u32 Bb[2][2], Bs[2][2];
#pragma unroll
            for (int j = 0; j < 2; j++) {
                const int ntj = 2 * w + j;
                const int b0 = ((k8 * 2 + 0) * 16 + ntj) * 33 + l;
                const int b1 = ((k8 * 2 + 1) * 16 + ntj) * 33 + l;
                Bb[j][0] = xbf[b0]; Bb[j][1] = xbf[b1];
                Bs[j][0] = xsf[b0]; Bs[j][1] = xsf[b1];
            }
#pragma unroll
            for (int mt = 0; mt < 9; mt++) {
                const int base = ((mt * 4 + k8) * 32 + l) * 4;
                u32 Ab[4], As[4];
                *(uint4*)Ab = *(const uint4*)&wbf[base];
                *(uint4*)As = *(const uint4*)&wsf[base];
#pragma unroll
                for (int j = 0; j < 2; j++) {
                    MMA_TF32(acc[mt][j], Ab, Bb[j]);
                    MMA_TF32(acc[mt][j], Ab, Bs[j]);
                    MMA_TF32(acc[mt][j], As, Bb[j]);
                }
            }
        }
    }

    const int gid = l >> 2, tig = l & 3;
#pragma unroll
    for (int mt = 0; mt < 9; mt++) {
#pragma unroll
        for (int j = 0; j < 2; j++) {
            int nb = n0 + (2 * w + j) * 8 + tig * 2;
#pragma unroll
            for (int half = 0; half < 2; half++) {
                int o = mt * 16 + gid + half * 8;
                float bias = g_bf[o];
                float* dst;
                if (o < 64)       dst = &g_q [((size_t)b * 64 + o)        * NN];
                else if (o < 80)  dst = &g_kf[((size_t)b * 16 + (o - 64)) * NN];
                else              dst = &g_v [((size_t)b * 64 + (o - 80)) * NN];
                float2 val = make_float2(acc[mt][j][half * 2 + 0] + bias,
                                         acc[mt][j][half * 2 + 1] + bias);
                *(float2*)&dst[nb] = val;
            }
        }
    }
}

// ============ K3: softmax over n for each (b,k) row ============
__global__ void softmax_kernel()
{
    int row = blockIdx.x;                 // b*16 + k
    float* p = &g_kf[(size_t)row * NN];
    int t = threadIdx.x;
    __shared__ float red[256];

    float vals[16];
    float m = -1e30f;
#pragma unroll
    for (int i = 0; i < 16; i++) {
        vals[i] = p[t + 256 * i];
        m = fmaxf(m, vals[i]);
    }
    red[t] = m; __syncthreads();
    for (int s = 128; s > 0; s >>= 1) {
        if (t < s) red[t] = fmaxf(red[t], red[t + s]);
        __syncthreads();
    }
    m = red[0]; __syncthreads();

    float sum = 0.f;
#pragma unroll
    for (int i = 0; i < 16; i++) {
        vals[i] = __expf(vals[i] - m);
        sum += vals[i];
    }
    red[t] = sum; __syncthreads();
    for (int s = 128; s > 0; s >>= 1) {
        if (t < s) red[t] += red[t + s];
        __syncthreads();
    }
    float inv = 1.f / red[0];
#pragma unroll
    for (int i = 0; i < 16; i++) p[t + 256 * i] = vals[i] * inv;
}

// ============ K4: lambda_c[b,k,v] = sum_n kf[b,k,n]*v[b,v,n] ============
__global__ void __launch_bounds__(256) lambdac_kernel()
{
    __shared__ float kfs[16][128];
    __shared__ float vs[64][129];
    int b = blockIdx.y;
    int n0 = blockIdx.x * 128;
    int t = threadIdx.x;

    for (int i = t; i < 16 * 128; i += 256) {
        int k = i >> 7, n = i & 127;
        kfs[k][n] = g_kf[((size_t)b * 16 + k) * NN + n0 + n];
    }
    for (int i = t; i < 64 * 128; i += 256) {
        int v = i >> 7, n = i & 127;
        vs[v][n] = g_v[((size_t)b * 64 + v) * NN + n0 + n];
    }
    __syncthreads();

#pragma unroll
    for (int pq = 0; pq < 4; pq++) {
        int pid = t + 256 * pq;           // 0..1023
        int k = pid >> 6, v = pid & 63;
        float a = 0.f;
#pragma unroll 8
        for (int nn = 0; nn < 128; nn++) a += kfs[k][nn] * vs[v][nn];
        atomicAdd(&g_lc[(size_t)b * 1024 + pid], a);
    }
}

// ============ K5: fused positional lambda + output (v9: tensor s-compute) ======
// s[h,dj,c] via mma.m16n8k8.tf32 (3-term): A = emb frags (global, precomputed),
// B = q tf32 frags in smem [c][68] (conflict-free). Apply loop unchanged.
// smem words: q_s 4096 @0 | lc_s 1024 @4096 | qtb 4352 @5120 | qts 4352 @9472
//             s_s [4h][23][68] 6256 @13824 | vr_s [64][88] 5632 @20080
//             total 25712 words = 102848 B
#define FUSED_SMEM_BYTES 102848

__global__ void __launch_bounds__(256, 2) fused_kernel(float* __restrict__ out)
{
    extern __shared__ float sm[];
    float* q_s  = sm;             // [64 ch][64 c]
    float* lc_s = sm + 4096;      // [16][64]
    u32*   qtb  = (u32*)(sm + 5120);   // [64 c][68]: q big tf32, transposed
    u32*   qts  = (u32*)(sm + 9472);   // residuals
    float* s_s  = sm + 13824;     // [4h][23dj][68]
    float* vr_s = sm + 20080;     // [64v][88]

    const int r = blockIdx.x, b = blockIdx.y;
    const int t = threadIdx.x;
    const int w = t >> 5, l = t & 31;

    // apply mapping: warp covers 8 strips x 4 vgroups (1-wf sh broadcasts)
    const int strip  = (l & 7) | ((w & 1) << 3);
    const int vgroup = (l >> 3) | ((w >> 1) << 2);
    const int c0 = strip * 4, v0 = vgroup * 4;

    // s-compute mma mapping: h per warp-pair, n-half per warp
    const int h_mma = w >> 1, nh = w & 1;

    // v-row fill mapping
    const int col = t & 63, vv0 = t >> 6;

    // ---- persistent tiles ----
    for (int i = t; i < 4096; i += 256) {
        int ch = i >> 6, c = i & 63;
        float qv = g_q[((size_t)b * 64 + ch) * NN + r * WH + c];
        q_s[i] = qv;
        u32 big = __float_as_uint(qv) & 0xFFFFE000u;
        float rs = qv - __uint_as_float(big);
        u32 sml = __float_as_uint(rs) & 0xFFFFE000u;
        qtb[c * 68 + ch] = big;
        qts[c * 68 + ch] = sml;
    }
    for (int i = t; i < 1024; i += 256) lc_s[i] = g_lc[b * 1024 + i];
    for (int i = t; i < 5632; i += 256) vr_s[i] = 0.f;   // halo stays zero
    __syncthreads();

    // ---- init acc with content lambda (scalar, exact q from q_s) ----
    float acc[4][4][4];
#pragma unroll
    for (int h = 0; h < 4; h++)
#pragma unroll
        for (int v = 0; v < 4; v++)
#pragma unroll
            for (int c = 0; c < 4; c++) acc[h][v][c] = 0.f;

    const float4* q4 = (const float4*)q_s;          // [64 ch][16] float4
#pragma unroll
    for (int k = 0; k < 16; k++) {
        float lv[4];
#pragma unroll
        for (int v = 0; v < 4; v++) lv[v] = lc_s[k * 64 + v0 + v];
#pragma unroll
        for (int h = 0; h < 4; h++) {
            float4 qv = q4[(h * 16 + k) * 16 + strip];
#pragma unroll
            for (int v = 0; v < 4; v++) {
                acc[h][v][0] += qv.x * lv[v]; acc[h][v][1] += qv.y * lv[v];
                acc[h][v][2] += qv.z * lv[v]; acc[h][v][3] += qv.w * lv[v];
            }
        }
    }

    const int di_lo = (r < PADK) ? (PADK - r) : 0;
    const int di_hi = (r > 52) ? (74 - r) : 22;
    const float* vbase = &g_v[(size_t)b * 64 * NN];

#pragma unroll 1
    for (int di = di_lo; di <= di_hi; di++) {
        const int rr = r + di - PADK;
        __syncthreads();   // A: previous apply done reading s_s / vr_s

        // prefetch v row (global, latency hidden behind s-compute)
        float vreg[16];
#pragma unroll
        for (int i = 0; i < 16; i++)
            vreg[i] = vbase[(size_t)(4 * i + vv0) * NN + rr * WH + col];

        // ---- s-compute via tensor cores ----
#pragma unroll
        for (int mt = 0; mt < 2; mt++) {
            u32 Ab[2][4], As[2][4];
#pragma unroll
            for (int k8 = 0; k8 < 2; k8++) {
                const int fb = ((di * 2 + mt) * 2 + k8) * 128 + l * 4;
                *(uint4*)Ab[k8] = *(const uint4*)&g_efb[fb];
                *(uint4*)As[k8] = *(const uint4*)&g_efs[fb];
            }
#pragma unroll
            for (int ntl = 0; ntl < 4; ntl++) {
                const int nt = nh * 4 + ntl;
                const int cB = nt * 8 + (l >> 2);
                u32 Bb[2][2], Bs[2][2];
#pragma unroll
                for (int k8 = 0; k8 < 2; k8++)
#pragma unroll
                    for (int slot = 0; slot < 2; slot++) {
                        const int kk = k8 * 8 + (l & 3) + slot * 4;
                        const int wrd = cB * 68 + h_mma * 16 + kk;
                        Bb[k8][slot] = qtb[wrd];
                        Bs[k8][slot] = qts[wrd];
                    }
                float D[4] = {0.f, 0.f, 0.f, 0.f};
#pragma unroll
                for (int k8 = 0; k8 < 2; k8++) {
                    MMA_TF32(D, Ab[k8], Bb[k8]);
                    MMA_TF32(D, Ab[k8], Bs[k8]);
                    MMA_TF32(D, As[k8], Bb[k8]);
                }
                const int dj0 = mt * 16 + (l >> 2);
                const int dj1 = dj0 + 8;
                const int cc = nt * 8 + 2 * (l & 3);
                if (dj0 < MMK)
                    *(float2*)&s_s[(h_mma * 23 + dj0) * 68 + cc] = make_float2(D[0], D[1]);
                if (dj1 < MMK)
                    *(float2*)&s_s[(h_mma * 23 + dj1) * 68 + cc] = make_float2(D[2], D[3]);
            }
        }

        // store prefetched v row
#pragma unroll
        for (int i = 0; i < 16; i++)
            vr_s[(4 * i + vv0) * 88 + PADK + col] = vreg[i];
        __syncthreads();   // B: s_s and vr_s ready

        // ---- apply: sliding 8-float window per v channel (unchanged) ----
        const float4* s4 = (const float4*)s_s;      // stride 17 float4 per dj row
        float vw[4][8];
#pragma unroll
        for (int v = 0; v < 4; v++) {
            float4 a0 = *(const float4*)&vr_s[(v0 + v) * 88 + c0];
            float4 a1 = *(const float4*)&vr_s[(v0 + v) * 88 + c0 + 4];
            vw[v][0] = a0.x; vw[v][1] = a0.y; vw[v][2] = a0.z; vw[v][3] = a0.w;
            vw[v][4] = a1.x; vw[v][5] = a1.y; vw[v][6] = a1.z; vw[v][7] = a1.w;
        }

#pragma unroll
        for (int djq = 0; djq < 6; djq++) {
#pragma unroll
            for (int djl = 0; djl < 4; djl++) {
                const int dj = djq * 4 + djl;
                if (dj < MMK) {
                    float4 sh[4];
#pragma unroll
                    for (int h = 0; h < 4; h++)
                        sh[h] = s4[(h * 23 + dj) * 17 + strip];
#pragma unroll
                    for (int h = 0; h < 4; h++)
#pragma unroll
                        for (int v = 0; v < 4; v++) {
                            acc[h][v][0] += sh[h].x * vw[v][djl + 0];
                            acc[h][v][1] += sh[h].y * vw[v][djl + 1];
                            acc[h][v][2] += sh[h].z * vw[v][djl + 2];
                            acc[h][v][3] += sh[h].w * vw[v][djl + 3];
                        }
                }
            }
            if (djq < 5) {
#pragma unroll
                for (int v = 0; v < 4; v++) {
                    vw[v][0] = vw[v][4]; vw[v][1] = vw[v][5];
                    vw[v][2] = vw[v][6]; vw[v][3] = vw[v][7];
                    float4 nx = *(const float4*)&vr_s[(v0 + v) * 88 + c0 + (djq + 2) * 4];
                    vw[v][4] = nx.x; vw[v][5] = nx.y; vw[v][6] = nx.z; vw[v][7] = nx.w;
                }
            }
        }
    }

    // ---- output ----
#pragma unroll
    for (int h = 0; h < 4; h++)
#pragma unroll
        for (int v = 0; v < 4; v++) {
            float4 o4 = make_float4(acc[h][v][0], acc[h][v][1],
                                    acc[h][v][2], acc[h][v][3]);
            *(float4*)&out[((size_t)b * 256 + h * 64 + v0 + v) * NN + r * WH + c0] = o4;
        }
}

// ============ launcher ============
extern "C" void kernel_launch(void* const* d_in, const int* in_sizes, int n_in,
                              void* d_out, int out_size)
{
    const float* x   = (const float*)d_in[0];
    const float* Wq  = (const float*)d_in[1];
    const float* qg  = (const float*)d_in[2];
    const float* qb  = (const float*)d_in[3];
    const float* qm  = (const float*)d_in[4];
    const float* qv  = (const float*)d_in[5];
    const float* Wk  = (const float*)d_in[6];
    const float* Wv  = (const float*)d_in[7];
    const float* vg  = (const float*)d_in[8];
    const float* vb  = (const float*)d_in[9];
    const float* vm  = (const float*)d_in[10];
    const float* vvr = (const float*)d_in[11];
    const float* emb = (const float*)d_in[12];
    float* out = (float*)d_out;

    cudaFuncSetAttribute(fused_kernel,
                         cudaFuncAttributeMaxDynamicSharedMemorySize,
                         FUSED_SMEM_BYTES);
    cudaFuncSetAttribute(proj_kernel,
                         cudaFuncAttributeMaxDynamicSharedMemorySize,
                         PROJ_SMEM_BYTES);

    fold_kernel<<<OCH, 256>>>(Wq, qg, qb, qm, qv, Wk, Wv, vg, vb, vm, vvr, emb);
    zero_lc_kernel<<<(BB * 16 * 64 + 255) / 256, 256>>>();
    proj_kernel<<<dim3(32, BB), 256, PROJ_SMEM_BYTES>>>(x);
    softmax_kernel<<<BB * 16, 256>>>();
    lambdac_kernel<<<dim3(32, BB), 256>>>();
    fused_kernel<<<dim3(WH, BB), 256, FUSED_SMEM_BYTES>>>(out);
}

// round 17
// speedup vs baseline: 1.3147x; 1.0713x over previous
#include <cuda_runtime.h>
#include <cstdint>
#include <math.h>

#define BB 8
#define CC 256
#define NN 4096        // 64*64
#define WH 64
#define MMK 23
#define PADK 11
#define OCH 144        // 64 q + 16 k + 64 v

typedef unsigned int u32;

#define MMA_TF32(d, a, b) \
    asm("mma.sync.aligned.m16n8k8.row.col.f32.tf32.tf32.f32 " \
        "{%0,%1,%2,%3}, {%4,%5,%6,%7}, {%8,%9}, {%0,%1,%2,%3};" \
        : "+f"((d)[0]), "+f"((d)[1]), "+f"((d)[2]), "+f"((d)[3]) \
        : "r"((a)[0]), "r"((a)[1]), "r"((a)[2]), "r"((a)[3]), \
          "r"((b)[0]), "r"((b)[1]))

// ---- scratch (static device globals; no allocation anywhere) ----
__device__ float g_Wf[OCH * CC];          // BN-folded weights
__device__ float g_bf[OCH];               // folded bias
__device__ __align__(16) u32 g_wbf[8 * 4608];  // W tf32 "big" frags (proj)
__device__ __align__(16) u32 g_wsf[8 * 4608];  // W tf32 residual frags
__device__ __align__(16) u32 g_efb[23 * 2 * 2 * 128];  // emb A-frags big
__device__ __align__(16) u32 g_efs[23 * 2 * 2 * 128];  // emb A-frags small
__device__ float g_q [BB * 64 * NN];      // q after BN
__device__ float g_kf[BB * 16 * NN];      // k, softmaxed in place
__device__ float g_v [BB * 64 * NN];      // v after BN
__device__ float g_lc[BB * 16 * 64];      // content lambda

// ============ K0: fold BN + precompute W frags + emb A-frags ============
__global__ void fold_kernel(const float* __restrict__ Wq,
                            const float* __restrict__ qg, const float* __restrict__ qb,
                            const float* __restrict__ qm, const float* __restrict__ qv,
                            const float* __restrict__ Wk, const float* __restrict__ Wv,
                            const float* __restrict__ vg, const float* __restrict__ vb,
                            const float* __restrict__ vm, const float* __restrict__ vvar,
                            const float* __restrict__ emb)
{
    int o = blockIdx.x;
    int c = threadIdx.x;
    float w, bias = 0.f;
    if (o < 64) {
        float s = qg[o] * rsqrtf(qv[o] + 1e-5f);
        w = Wq[o * CC + c] * s;
        bias = qb[o] - qm[o] * s;
    } else if (o < 80) {
        int oo = o - 64;
        w = Wk[oo * CC + c];
    } else {
        int oo = o - 80;
        float s = vg[oo] * rsqrtf(vvar[oo] + 1e-5f);
        w = Wv[oo * CC + c] * s;
        bias = vb[oo] - vm[oo] * s;
    }
    g_Wf[o * CC + c] = w;
    if (c == 0) g_bf[o] = bias;

    // W tf32 fragments (validated in r15)
    {
        int chunk = c >> 5, k = c & 31;
        u32 big = __float_as_uint(w) & 0xFFFFE000u;
        float rs = w - __uint_as_float(big);
        u32 sml = __float_as_uint(rs) & 0xFFFFE000u;
        int word = chunk * 4608
                 + (((o >> 4) * 4 + (k >> 3)) * 32 + (o & 7) * 4 + (k & 3)) * 4
                 + ((o >> 3) & 1) + (((k >> 2) & 1) << 1);
        g_wbf[word] = big;
        g_wsf[word] = sml;
    }

    // emb A-fragments: per di, A[dj(pad 32)][k 16], same swizzle as W
    if (o < MMK) {
#pragma unroll
        for (int e = 0; e < 2; e++) {
            int idx = c + 256 * e;        // 0..511
            int dj = idx >> 4;            // 0..31
            int k  = idx & 15;
            float val = (dj < MMK) ? emb[k * 529 + o * MMK + dj] : 0.f;
            u32 big = __float_as_uint(val) & 0xFFFFE000u;
            float rs = val - __uint_as_float(big);
            u32 sml = __float_as_uint(rs) & 0xFFFFE000u;
            int word = ((o * 2 + (dj >> 4)) * 2 + (k >> 3)) * 128
                     + ((dj & 7) * 4 + (k & 3)) * 4
                     + ((dj >> 3) & 1) + (((k >> 2) & 1) << 1);
            g_efb[word] = big;
            g_efs[word] = sml;
        }
    }
}

// ============ K1: zero lambda_c (graph replays -> must re-zero) ============
__global__ void zero_lc_kernel()
{
    int i = blockIdx.x * 256 + threadIdx.x;
    if (i < BB * 16 * 64) g_lc[i] = 0.f;
}

// ============ K2: projection GEMM via tf32 tensor cores (r15, proven) ============
#define PROJ_SMEM_BYTES 70656

__global__ void __launch_bounds__(256, 2) proj_kernel(const float* __restrict__ x)
{
    extern __shared__ u32 smu[];
    u32* wbf = smu;            // [9 mt][4 k8][32 lane][4 slot]
    u32* wsf = smu + 4608;
    u32* xbf = smu + 9216;     // [4 k8][2 slot][16 nt][33]
    u32* xsf = smu + 13440;

    const int b = blockIdx.y;
    const int n0 = blockIdx.x * 128;
    const int t = threadIdx.x;
    const int w = t >> 5, l = t & 31;

    const int k0 = t >> 5;
    const int n4 = t & 31;
    const int slotX = (k0 >> 2) & 1;
    const int k3 = k0 & 3;

    float acc[9][2][4];
#pragma unroll
    for (int mt = 0; mt < 9; mt++)
#pragma unroll
        for (int j = 0; j < 2; j++)
#pragma unroll
            for (int e = 0; e < 4; e++) acc[mt][j][e] = 0.f;

#pragma unroll 1
    for (int kc = 0; kc < CC; kc += 32) {
        __syncthreads();
        const int chunk = kc >> 5;

        {
            const uint4* srcb = (const uint4*)(g_wbf + chunk * 4608);
            const uint4* srcs = (const uint4*)(g_wsf + chunk * 4608);
            for (int i = t; i < 1152; i += 256) {
                ((uint4*)wbf)[i] = srcb[i];
                ((uint4*)wsf)[i] = srcs[i];
            }
        }
#pragma unroll
        for (int m = 0; m < 4; m++) {
            const int k = k0 + 8 * m;
            float4 xv = *(const float4*)&x[((size_t)b * CC + kc + k) * NN + n0 + n4 * 4];
            float vals[4] = {xv.x, xv.y, xv.z, xv.w};
#pragma unroll
            for (int e = 0; e < 4; e++) {
                const int n = n4 * 4 + e;
                u32 big = __float_as_uint(vals[e]) & 0xFFFFE000u;
                float rs = vals[e] - __uint_as_float(big);
                u32 sml = __float_as_uint(rs) & 0xFFFFE000u;
                int word = ((m * 2 + slotX) * 16 + (n >> 3)) * 33 + (n & 7) * 4 + k3;
                xbf[word] = big;
                xsf[word] = sml;
            }
        }
        __syncthreads();

#pragma unroll
        for (int k8 = 0; k8 < 4; k8++) {
            u32 Bb[2][2], Bs[2][2];
#pragma unroll
            for (int j = 0; j < 2; j++) {
                const int ntj = 2 * w + j;
                const int b0 = ((k8 * 2 + 0) * 16 + ntj) * 33 + l;
                const int b1 = ((k8 * 2 + 1) * 16 + ntj) * 33 + l;
                Bb[j][0] = xbf[b0]; Bb[j][1] = xbf[b1];
                Bs[j][0] = xsf[b0]; Bs[j][1] = xsf[b1];
            }
#pragma unroll
            for (int mt = 0; mt < 9; mt++) {
                const int base = ((mt * 4 + k8) * 32 + l) * 4;
                u32 Ab[4], As[4];
                *(uint4*)Ab = *(const uint4*)&wbf[base];
                *(uint4*)As = *(const uint4*)&wsf[base];
#pragma unroll
                for (int j = 0; j < 2; j++) {
                    MMA_TF32(acc[mt][j], Ab, Bb[j]);
                    MMA_TF32(acc[mt][j], Ab, Bs[j]);
                    MMA_TF32(acc[mt][j], As, Bb[j]);
                }
            }
        }
    }

    const int gid = l >> 2, tig = l & 3;
#pragma unroll
    for (int mt = 0; mt < 9; mt++) {
#pragma unroll
        for (int j = 0; j < 2; j++) {
            int nb = n0 + (2 * w + j) * 8 + tig * 2;
#pragma unroll
            for (int half = 0; half < 2; half++) {
                int o = mt * 16 + gid + half * 8;
                float bias = g_bf[o];
                float* dst;
                if (o < 64)       dst = &g_q [((size_t)b * 64 + o)        * NN];
                else if (o < 80)  dst = &g_kf[((size_t)b * 16 + (o - 64)) * NN];
                else              dst = &g_v [((size_t)b * 64 + (o - 80)) * NN];
                float2 val = make_float2(acc[mt][j][half * 2 + 0] + bias,
                                         acc[mt][j][half * 2 + 1] + bias);
                *(float2*)&dst[nb] = val;
            }
        }
    }
}

// ============ K3: softmax over n for each (b,k) row ============
__global__ void softmax_kernel()
{
    int row = blockIdx.x;                 // b*16 + k
    float* p = &g_kf[(size_t)row * NN];
    int t = threadIdx.x;
    __shared__ float red[256];

    float vals[16];
    float m = -1e30f;
#pragma unroll
    for (int i = 0; i < 16; i++) {
        vals[i] = p[t + 256 * i];
        m = fmaxf(m, vals[i]);
    }
    red[t] = m; __syncthreads();
    for (int s = 128; s > 0; s >>= 1) {
        if (t < s) red[t] = fmaxf(red[t], red[t + s]);
        __syncthreads();
    }
    m = red[0]; __syncthreads();

    float sum = 0.f;
#pragma unroll
    for (int i = 0; i < 16; i++) {
        vals[i] = __expf(vals[i] - m);
        sum += vals[i];
    }
    red[t] = sum; __syncthreads();
    for (int s = 128; s > 0; s >>= 1) {
        if (t < s) red[t] += red[t + s];
        __syncthreads();
    }
    float inv = 1.f / red[0];
#pragma unroll
    for (int i = 0; i < 16; i++) p[t + 256 * i] = vals[i] * inv;
}

// ============ K4: lambda_c[b,k,v] = sum_n kf[b,k,n]*v[b,v,n] ============
__global__ void __launch_bounds__(256) lambdac_kernel()
{
    __shared__ float kfs[16][128];
    __shared__ float vs[64][129];
    int b = blockIdx.y;
    int n0 = blockIdx.x * 128;
    int t = threadIdx.x;

    for (int i = t; i < 16 * 128; i += 256) {
        int k = i >> 7, n = i & 127;
        kfs[k][n] = g_kf[((size_t)b * 16 + k) * NN + n0 + n];
    }
    for (int i = t; i < 64 * 128; i += 256) {
        int v = i >> 7, n = i & 127;
        vs[v][n] = g_v[((size_t)b * 64 + v) * NN + n0 + n];
    }
    __syncthreads();

#pragma unroll
    for (int pq = 0; pq < 4; pq++) {
        int pid = t + 256 * pq;           // 0..1023
        int k = pid >> 6, v = pid & 63;
        float a = 0.f;
#pragma unroll 8
        for (int nn = 0; nn < 128; nn++) a += kfs[k][nn] * vs[v][nn];
        atomicAdd(&g_lc[(size_t)b * 1024 + pid], a);
    }
}

// ============ K5: fused positional lambda + output (v10 = v9 + LPT schedule) ===
// Grid is 1-D (512). bid -> (b = bid&7, s = bid>>3); s -> row via heavy-first
// permutation: interior rows (23 di) launch first across all batches, boundary
// rows (12..22 di) last -> short tail wave (LPT scheduling).
#define FUSED_SMEM_BYTES 102848

__global__ void __launch_bounds__(256, 2) fused_kernel(float* __restrict__ out)
{
    extern __shared__ float sm[];
    float* q_s  = sm;             // [64 ch][64 c]
    float* lc_s = sm + 4096;      // [16][64]
    u32*   qtb  = (u32*)(sm + 5120);   // [64 c][68]: q big tf32, transposed
    u32*   qts  = (u32*)(sm + 9472);   // residuals
    float* s_s  = sm + 13824;     // [4h][23dj][68]
    float* vr_s = sm + 20080;     // [64v][88]

    // ---- LPT block -> (row, batch) permutation ----
    const int bid = blockIdx.x;
    const int b = bid & 7;
    const int sidx = bid >> 3;            // 0..63, heavy-first
    int r;
    if (sidx < 42) {
        r = 11 + sidx;                    // interior: 23 di
    } else {
        int j = sidx - 42, p = j >> 1;    // boundary pairs, descending di
        r = (j & 1) ? (53 + p) : (10 - p);
    }

    const int t = threadIdx.x;
    const int w = t >> 5, l = t & 31;

    // apply mapping: warp covers 8 strips x 4 vgroups (1-wf sh broadcasts)
    const int strip  = (l & 7) | ((w & 1) << 3);
    const int vgroup = (l >> 3) | ((w >> 1) << 2);
    const int c0 = strip * 4, v0 = vgroup * 4;

    // s-compute mma mapping: h per warp-pair, n-half per warp
    const int h_mma = w >> 1, nh = w & 1;

    // v-row fill mapping
    const int col = t & 63, vv0 = t >> 6;

    // ---- persistent tiles ----
    for (int i = t; i < 4096; i += 256) {
        int ch = i >> 6, c = i & 63;
        float qv = g_q[((size_t)b * 64 + ch) * NN + r * WH + c];
        q_s[i] = qv;
        u32 big = __float_as_uint(qv) & 0xFFFFE000u;
        float rs = qv - __uint_as_float(big);
        u32 sml = __float_as_uint(rs) & 0xFFFFE000u;
        qtb[c * 68 + ch] = big;
        qts[c * 68 + ch] = sml;
    }
    for (int i = t; i < 1024; i += 256) lc_s[i] = g_lc[b * 1024 + i];
    for (int i = t; i < 5632; i += 256) vr_s[i] = 0.f;   // halo stays zero
    __syncthreads();

    // ---- init acc with content lambda (scalar, exact q from q_s) ----
    float acc[4][4][4];
#pragma unroll
    for (int h = 0; h < 4; h++)
#pragma unroll
        for (int v = 0; v < 4; v++)
#pragma unroll
            for (int c = 0; c < 4; c++) acc[h][v][c] = 0.f;

    const float4* q4 = (const float4*)q_s;          // [64 ch][16] float4
#pragma unroll
    for (int k = 0; k < 16; k++) {
        float lv[4];
#pragma unroll
        for (int v = 0; v < 4; v++) lv[v] = lc_s[k * 64 + v0 + v];
#pragma unroll
        for (int h = 0; h < 4; h++) {
            float4 qv = q4[(h * 16 + k) * 16 + strip];
#pragma unroll
            for (int v = 0; v < 4; v++) {
                acc[h][v][0] += qv.x * lv[v]; acc[h][v][1] += qv.y * lv[v];
                acc[h][v][2] += qv.z * lv[v]; acc[h][v][3] += qv.w * lv[v];
            }
        }
    }

    const int di_lo = (r < PADK) ? (PADK - r) : 0;
    const int di_hi = (r > 52) ? (74 - r) : 22;
    const float* vbase = &g_v[(size_t)b * 64 * NN];

#pragma unroll 1
    for (int di = di_lo; di <= di_hi; di++) {
        const int rr = r + di - PADK;
        __syncthreads();   // A: previous apply done reading s_s / vr_s

        // prefetch v row (global, latency hidden behind s-compute)
        float vreg[16];
#pragma unroll
        for (int i = 0; i < 16; i++)
            vreg[i] = vbase[(size_t)(4 * i + vv0) * NN + rr * WH + col];

        // ---- s-compute via tensor cores ----
#pragma unroll
        for (int mt = 0; mt < 2; mt++) {
            u32 Ab[2][4], As[2][4];
#pragma unroll
            for (int k8 = 0; k8 < 2; k8++) {
                const int fb = ((di * 2 + mt) * 2 + k8) * 128 + l * 4;
                *(uint4*)Ab[k8] = *(const uint4*)&g_efb[fb];
                *(uint4*)As[k8] = *(const uint4*)&g_efs[fb];
            }
#pragma unroll
            for (int ntl = 0; ntl < 4; ntl++) {
                const int nt = nh * 4 + ntl;
                const int cB = nt * 8 + (l >> 2);
                u32 Bb[2][2], Bs[2][2];
#pragma unroll
                for (int k8 = 0; k8 < 2; k8++)
#pragma unroll
                    for (int slot = 0; slot < 2; slot++) {
                        const int kk = k8 * 8 + (l & 3) + slot * 4;
                        const int wrd = cB * 68 + h_mma * 16 + kk;
                        Bb[k8][slot] = qtb[wrd];
                        Bs[k8][slot] = qts[wrd];
                    }
                float D[4] = {0.f, 0.f, 0.f, 0.f};
#pragma unroll
                for (int k8 = 0; k8 < 2; k8++) {
                    MMA_TF32(D, Ab[k8], Bb[k8]);
                    MMA_TF32(D, Ab[k8], Bs[k8]);
                    MMA_TF32(D, As[k8], Bb[k8]);
                }
                const int dj0 = mt * 16 + (l >> 2);
                const int dj1 = dj0 + 8;
                const int cc = nt * 8 + 2 * (l & 3);
                if (dj0 < MMK)
                    *(float2*)&s_s[(h_mma * 23 + dj0) * 68 + cc] = make_float2(D[0], D[1]);
                if (dj1 < MMK)
                    *(float2*)&s_s[(h_mma * 23 + dj1) * 68 + cc] = make_float2(D[2], D[3]);
            }
        }

        // store prefetched v row
#pragma unroll
        for (int i = 0; i < 16; i++)
            vr_s[(4 * i + vv0) * 88 + PADK + col] = vreg[i];
        __syncthreads();   // B: s_s and vr_s ready

        // ---- apply: sliding 8-float window per v channel (unchanged) ----
        const float4* s4 = (const float4*)s_s;      // stride 17 float4 per dj row
        float vw[4][8];
#pragma unroll
        for (int v = 0; v < 4; v++) {
            float4 a0 = *(const float4*)&vr_s[(v0 + v) * 88 + c0];
            float4 a1 = *(const float4*)&vr_s[(v0 + v) * 88 + c0 + 4];
            vw[v][0] = a0.x; vw[v][1] = a0.y; vw[v][2] = a0.z; vw[v][3] = a0.w;
            vw[v][4] = a1.x; vw[v][5] = a1.y; vw[v][6] = a1.z; vw[v][7] = a1.w;
        }

#pragma unroll
        for (int djq = 0; djq < 6; djq++) {
#pragma unroll
            for (int djl = 0; djl < 4; djl++) {
                const int dj = djq * 4 + djl;
                if (dj < MMK) {
                    float4 sh[4];
#pragma unroll
                    for (int h = 0; h < 4; h++)
                        sh[h] = s4[(h * 23 + dj) * 17 + strip];
#pragma unroll
                    for (int h = 0; h < 4; h++)
#pragma unroll
                        for (int v = 0; v < 4; v++) {
                            acc[h][v][0] += sh[h].x * vw[v][djl + 0];
                            acc[h][v][1] += sh[h].y * vw[v][djl + 1];
                            acc[h][v][2] += sh[h].z * vw[v][djl + 2];
                            acc[h][v][3] += sh[h].w * vw[v][djl + 3];
                        }
                }
            }
            if (djq < 5) {
#pragma unroll
                for (int v = 0; v < 4; v++) {
                    vw[v][0] = vw[v][4]; vw[v][1] = vw[v][5];
                    vw[v][2] = vw[v][6]; vw[v][3] = vw[v][7];
                    float4 nx = *(const float4*)&vr_s[(v0 + v) * 88 + c0 + (djq + 2) * 4];
                    vw[v][4] = nx.x; vw[v][5] = nx.y; vw[v][6] = nx.z; vw[v][7] = nx.w;
                }
            }
        }
    }

    // ---- output ----
#pragma unroll
    for (int h = 0; h < 4; h++)
#pragma unroll
        for (int v = 0; v < 4; v++) {
            float4 o4 = make_float4(acc[h][v][0], acc[h][v][1],
                                    acc[h][v][2], acc[h][v][3]);
            *(float4*)&out[((size_t)b * 256 + h * 64 + v0 + v) * NN + r * WH + c0] = o4;
        }
}

// ============ launcher ============
extern "C" void kernel_launch(void* const* d_in, const int* in_sizes, int n_in,
                              void* d_out, int out_size)
{
    const float* x   = (const float*)d_in[0];
    const float* Wq  = (const float*)d_in[1];
    const float* qg  = (const float*)d_in[2];
    const float* qb  = (const float*)d_in[3];
    const float* qm  = (const float*)d_in[4];
    const float* qv  = (const float*)d_in[5];
    const float* Wk  = (const float*)d_in[6];
    const float* Wv  = (const float*)d_in[7];
    const float* vg  = (const float*)d_in[8];
    const float* vb  = (const float*)d_in[9];
    const float* vm  = (const float*)d_in[10];
    const float* vvr = (const float*)d_in[11];
    const float* emb = (const float*)d_in[12];
    float* out = (float*)d_out;

    cudaFuncSetAttribute(fused_kernel,
                         cudaFuncAttributeMaxDynamicSharedMemorySize,
                         FUSED_SMEM_BYTES);
    cudaFuncSetAttribute(proj_kernel,
                         cudaFuncAttributeMaxDynamicSharedMemorySize,
                         PROJ_SMEM_BYTES);

    fold_kernel<<<OCH, 256>>>(Wq, qg, qb, qm, qv, Wk, Wv, vg, vb, vm, vvr, emb);
    zero_lc_kernel<<<(BB * 16 * 64 + 255) / 256, 256>>>();
    proj_kernel<<<dim3(32, BB), 256, PROJ_SMEM_BYTES>>>(x);
    softmax_kernel<<<BB * 16, 256>>>();
    lambdac_kernel<<<dim3(32, BB), 256>>>();
    fused_kernel<<<512, 256, FUSED_SMEM_BYTES>>>(out);
}